// round 14
// baseline (speedup 1.0000x reference)
#include <cuda_runtime.h>

// SparseMCFModel — math reduction (validated over 12 passing rounds):
//  * decoder softmax has identical logits within each segment
//    => w[e] = 1/out_degree(edge_row[e]) EXACTLY. GAT/GRU/decoder dead code.
//  * recurrence: x_1 = relu(demands);
//      x_{t+1}[n] = dpos[n] + sum_{e: col(e)=n} w[e]*x_t[row(e)]
//      flow[e]    = w[e] * x_10[row(e)]
//
// Structure: PDL-chained 11-node graph, HALF-MACHINE grids (2 edges/thread,
// 391 blocks x 256) so predecessor + dependent are fully co-resident.
//
// R13 post-mortem: trigger-BEFORE-wait lets 3 generations run concurrently
// (t+1 pre-wait vs t-1 execution) -> t+1's reset of x[(t+2)%4] == x[(t-2)%4]
// clobbered t-1's read buffer. FIX: pdl_trigger AFTER pdl_wait in all
// dependent kernels => at most 2 generations overlap; 4-buffer rotation is
// then provably race-free (reset x[(t+1)%4] vs t-1's set {t-2,t-1,t}%4).
// k_init_deg additionally pre-resets x[2] so k_upd_first's pre-wait phase
// touches ONLY pure harness inputs.

#define NN  20000
#define NE  200000
#define NE2 (NE / 2)
#define BS  256
#define GB  ((NE2 + BS - 1) / BS)   // 391 blocks (half machine)

__device__ float  d_dpos[NN];
__device__ float  d_x[4][NN];
__device__ int    d_deg[NN];    // zero at replay start (static init / k_final rezero)
__device__ float2 d_w2[NE2];    // per-edge weights (written by k_upd_first only)

__device__ __forceinline__ void pdl_trigger() {
    asm volatile("griddepcontrol.launch_dependents;" ::: "memory");
}
__device__ __forceinline__ void pdl_wait() {
    asm volatile("griddepcontrol.wait;" ::: "memory");
}

// node 1: node-init (x[0..2] = dpos) + degree histogram (2 edges/thread).
// Early trigger OK: dependent (k_upd_first) pre-wait reads only pure inputs.
__global__ void __launch_bounds__(BS) k_init_deg(const float* __restrict__ demands,
                                                 const int* __restrict__ row) {
    int i = blockIdx.x * BS + threadIdx.x;
    pdl_trigger();
    if (i < NN / 2) {
        float2 d = __ldg((const float2*)demands + i);
        d.x = d.x > 0.0f ? d.x : 0.0f;
        d.y = d.y > 0.0f ? d.y : 0.0f;
        ((float2*)d_dpos)[i] = d;
        ((float2*)d_x[0])[i] = d;     // x_1 (read buffer of step 1)
        ((float2*)d_x[1])[i] = d;     // step 1 write target, pre-reset
        ((float2*)d_x[2])[i] = d;     // step 2 write target, pre-reset
    }
    if (i < NE2) {
        int2 r = __ldg((const int2*)row + i);
        atomicAdd(&d_deg[r.x], 1);
        atomicAdd(&d_deg[r.y], 1);
    }
}

// node 2 (step 1): x_1 -> x_2 + weight precompute. Pre-wait: pure inputs only.
__global__ void __launch_bounds__(BS) k_upd_first(const int* __restrict__ row,
                                                  const int* __restrict__ col) {
    int i = blockIdx.x * BS + threadIdx.x;
    int2 r = make_int2(0, 0), c = make_int2(0, 0);
    if (i < NE2) { r = __ldg((const int2*)row + i); c = __ldg((const int2*)col + i); }
    pdl_wait();                            // init + deg complete + visible
    pdl_trigger();                         // now step 2 may start its pre-wait
    if (i < NE2) {
        float2 w;
        w.x = 1.0f / (float)d_deg[r.x];
        w.y = 1.0f / (float)d_deg[r.y];
        d_w2[i] = w;
        atomicAdd(&d_x[1][c.x], w.x * d_x[0][r.x]);
        atomicAdd(&d_x[1][c.y], w.y * d_x[0][r.y]);
    }
}

// nodes 3..10 (steps 2..9): 4-buffer rotation, 2 edges/thread.
// Pre-wait phase overlaps ONLY step t-1 (trigger-after-wait): may read pure
// inputs, d_w2 (immutable; except step 2: writer is t-1 => wpost), d_dpos
// (immutable), and reset x[(t+1)%4] (disjoint from t-1's buffers).
__global__ void __launch_bounds__(BS) k_update(const int* __restrict__ row,
                                               const int* __restrict__ col,
                                               int cur, int nxt, int rst, int wpost) {
    int i = blockIdx.x * BS + threadIdx.x;
    int2 r = make_int2(0, 0), c = make_int2(0, 0);
    float2 w = make_float2(0.f, 0.f);
    if (i < NE2) {
        r = __ldg((const int2*)row + i);
        c = __ldg((const int2*)col + i);
        if (!wpost) w = d_w2[i];
    }
    if (i < NN) d_x[rst][i] = d_dpos[i];   // pre-wait reset (safe: 2-gen overlap)
    pdl_wait();                            // step t-1 complete + visible
    pdl_trigger();                         // release step t+1's pre-wait
    if (i < NE2) {
        if (wpost) w = d_w2[i];
        float ax = __ldg(&d_x[cur][r.x]);  // 2 independent gathers (MLP)
        float ay = __ldg(&d_x[cur][r.y]);
        atomicAdd(&d_x[nxt][c.x], w.x * ax);
        atomicAdd(&d_x[nxt][c.y], w.y * ay);
    }
}

// node 11: flow = w * x_10[row]. Pre-wait: inputs, d_w2 (immutable),
// deg rezero (no concurrent toucher).
__global__ void __launch_bounds__(BS) k_final(const int* __restrict__ row,
                                              float* __restrict__ out, int cur) {
    int i = blockIdx.x * BS + threadIdx.x;
    int2 r = make_int2(0, 0);
    float2 w = make_float2(0.f, 0.f);
    if (i < NE2) { r = __ldg((const int2*)row + i); w = d_w2[i]; }
    if (i < NN) d_deg[i] = 0;              // rezero for next replay
    pdl_wait();
    if (i < NE2) {
        float2 o;
        o.x = w.x * __ldg(&d_x[cur][r.x]);
        o.y = w.y * __ldg(&d_x[cur][r.y]);
        ((float2*)out)[i] = o;
    }
}

static inline void launch_pdl(const void* fn, void** args) {
    cudaLaunchConfig_t cfg = {};
    cfg.gridDim  = dim3(GB);
    cfg.blockDim = dim3(BS);
    cfg.dynamicSmemBytes = 0;
    cfg.stream = 0;
    cudaLaunchAttribute at;
    at.id = cudaLaunchAttributeProgrammaticStreamSerialization;
    at.val.programmaticStreamSerializationAllowed = 1;
    cfg.attrs = &at;
    cfg.numAttrs = 1;
    if (cudaLaunchKernelExC(&cfg, fn, args) != cudaSuccess) {
        cudaGetLastError();
        cfg.numAttrs = 0;                  // fallback: serialized launch (wait is benign)
        cudaLaunchKernelExC(&cfg, fn, args);
    }
}

extern "C" void kernel_launch(void* const* d_in, const int* in_sizes, int n_in,
                              void* d_out, int out_size) {
    // Inputs: node_embeddings, demands, edge_row, edge_col, W_gat, a_src,
    //         a_dst, Wx, Wh, b_gru, Wd, bd
    const float* demands = (const float*)d_in[1];
    const int*   erow    = (const int*)d_in[2];
    const int*   ecol    = (const int*)d_in[3];
    float*       out     = (float*)d_out;

    k_init_deg<<<GB, BS>>>(demands, erow);

    {
        void* args[2] = { (void*)&erow, (void*)&ecol };
        launch_pdl((const void*)k_upd_first, args);
    }

    // steps 2..9: read x[(t-1)%4], write x[t%4], reset x[(t+1)%4]
    for (int t = 2; t <= 9; t++) {
        int cur = (t - 1) & 3, nxt = t & 3, rst = (t + 1) & 3;
        int wpost = (t == 2) ? 1 : 0;
        void* args[6] = { (void*)&erow, (void*)&ecol, &cur, &nxt, &rst, &wpost };
        launch_pdl((const void*)k_update, args);
    }

    {
        int cur = 9 & 3;   // x_10 lives in d_x[1]
        void* args[3] = { (void*)&erow, (void*)&out, &cur };
        launch_pdl((const void*)k_final, args);
    }
}